// round 16
// baseline (speedup 1.0000x reference)
#include <cuda_runtime.h>

// Problem constants (fixed shapes from reference)
#define B_  32
#define C_  64
#define H_  112
#define MH_ 28      // coarse grid = H/4
#define G_  4

// Scratch (no cudaMalloc allowed). All plain-stored each run -> no resets needed.
// __align__(16): gA is bulk-copied with uint4 (LDG.128) in the finalize CTA --
// unaligned placement of a char array caused the R15 "misaligned address" trap.
__device__ __align__(16) unsigned char gA[B_ * MH_ * MH_];   // coarse any-group mask (0/1)
__device__ __align__(16) unsigned int  g_cnt_mask[B_ * MH_]; // per (b,i) coarse mask count

// ---------------------------------------------------------------------------
// Kernel 1 (~19.5us measured R12): one CTA per (b, i), 256 threads.
// ---------------------------------------------------------------------------
__global__ __launch_bounds__(256)
void k_pool_mask(const float* __restrict__ x,
                 const float* __restrict__ w,       // (8,64)
                 const float* __restrict__ bias,    // (8,)
                 const float* __restrict__ gumbel,  // (B,2,G,28,28)
                 float* __restrict__ out_mask)      // (B,G,112,112)
{
    const int i   = blockIdx.x;   // coarse row 0..27
    const int b   = blockIdx.y;   // batch
    const int tid = threadIdx.x;

    __shared__ float sw[8 * 64];
    __shared__ float sb[8];
    __shared__ float sg[224];       // gumbel slice [2][4][28] for (b, i)
    __shared__ float sm[64 * 28];   // pooled means
    __shared__ float sl[8 * 28];    // logits
    __shared__ float sM[4 * 28];    // coarse mask (0/1)
    __shared__ unsigned int scnt;

    // Prefetch gumbel FIRST (issues ahead of the big x burst -> off the tail).
    if (tid < 224) {
        const int o2 = tid / 112, rem = tid % 112;
        const int g = rem / 28, j = rem % 28;
        sg[tid] = gumbel[(((size_t)(b * 2 + o2) * 4 + g) * 28 + i) * 28 + j];
    }
    // 512 weights, 256 threads -> two loads per thread.
    sw[tid]       = w[tid];
    sw[tid + 256] = w[tid + 256];
    if (tid < 8)  sb[tid] = bias[tid];
    if (tid == 0) scnt = 0u;

    // ---- Phase 1: pooling (HBM-bound term: 112 KB per CTA) ----
    {
        const float* xb = x + ((size_t)b * 64 * 112 + (size_t)i * 4) * 112;
        #pragma unroll
        for (int k = 0; k < 7; k++) {
            const int t = tid + k * 256;
            const int c = t / 28, j = t % 28;
            const float* p = xb + (size_t)c * (112 * 112) + j * 4;
            float s = 0.f;
            #pragma unroll
            for (int r = 0; r < 4; r++) {
                const float4 v = *reinterpret_cast<const float4*>(p + r * 112);
                s += v.x + v.y + v.z + v.w;
            }
            sm[c * 28 + j] = s * (1.0f / 16.0f);
        }
    }
    __syncthreads();

    // ---- Phase 2: logits (8 outputs x 28 cells) ----
    if (tid < 8 * 28) {
        const int o = tid / 28, j = tid % 28;
        float acc = sb[o];
        #pragma unroll
        for (int c = 0; c < 64; c++)
            acc += sw[o * 64 + c] * sm[c * 28 + j];
        sl[o * 28 + j] = acc;
    }
    __syncthreads();

    // ---- Phase 3: gumbel argmax -> coarse mask (gumbel from smem) ----
    if (tid < 4 * 28) {
        const int g = tid / 28, j = tid % 28;
        const float v0 = sl[g * 28 + j]       + sg[g * 28 + j];
        const float v1 = sl[(4 + g) * 28 + j] + sg[112 + g * 28 + j];
        const float m  = (v0 >= v1) ? 1.0f : 0.0f;   // jnp.argmax: first index wins ties
        sM[g * 28 + j] = m;
        if (m > 0.f) atomicAdd(&scnt, 1u);           // smem atomic only
    }
    __syncthreads();

    if (tid < 28) {
        const unsigned char a =
            (sM[tid] != 0.f) | (sM[28 + tid] != 0.f) |
            (sM[56 + tid] != 0.f) | (sM[84 + tid] != 0.f);
        gA[(b * 28 + i) * 28 + tid] = a;
    }
    if (tid == 0) g_cnt_mask[b * 28 + i] = scnt;     // plain store, no ATOMG

    // ---- Phase 4: fine mask, float4 stores (4 groups x 4 rows x 28 float4) ----
    for (int t = tid; t < 4 * 4 * 28; t += 256) {
        const int g  = t / 112;
        const int r  = (t / 28) & 3;
        const int cj = t % 28;
        const float v = sM[g * 28 + cj];
        float4* dst = reinterpret_cast<float4*>(
            out_mask + (((size_t)(b * 4 + g) * 112) + (i * 4 + r)) * 112) + cj;
        *dst = make_float4(v, v, v, v);
    }
}

// ---------------------------------------------------------------------------
// Kernel 2 v3: pure-store dilation + closed-form finalize in CTA (0,0).
// Grid (28, 32) = 896 CTAs, 256 threads. NO global atomics, NO ticket, NO
// fences -> nothing serialized, nothing to reset, replay-deterministic.
// ---------------------------------------------------------------------------
__global__ __launch_bounds__(256)
void k_dil(float* __restrict__ out_dil,     // (B,G,112,112)
           float* __restrict__ out_scal)
{
    const int i   = blockIdx.x;   // coarse row
    const int b   = blockIdx.y;
    const int tid = threadIdx.x;

    __shared__ unsigned char rT[MH_], rM[MH_], rB[MH_];
    __shared__ __align__(16) unsigned char sAll[B_ * MH_ * MH_];  // finalize CTA only
    __shared__ unsigned int red[256];

    if (tid < 28) {
        const unsigned char* Ab = gA + (size_t)b * 784;
        const unsigned char m = Ab[i * 28 + tid];
        rM[tid] = m;
        rT[tid] = (i > 0 ) ? (unsigned char)(Ab[(i - 1) * 28 + tid] | m) : m;
        rB[tid] = (i < 27) ? (unsigned char)(Ab[(i + 1) * 28 + tid] | m) : m;
    }
    __syncthreads();

    // items: r(4) x g(4) x cj(28) = 448; threads handle t and t+256.
    #pragma unroll
    for (int it = 0; it < 2; it++) {
        const int t = tid + it * 256;
        if (t < 448) {
            const int r   = t / 112;
            const int rem = t % 112;
            const int g   = rem / 28;
            const int cj  = rem % 28;
            const unsigned char* row = (r == 0) ? rT : ((r == 3) ? rB : rM);
            const unsigned char mid = row[cj];
            const unsigned char lft = (cj > 0 ) ? (unsigned char)(mid | row[cj - 1]) : mid;
            const unsigned char rgt = (cj < 27) ? (unsigned char)(mid | row[cj + 1]) : mid;
            const int h = i * 4 + r;
            reinterpret_cast<float4*>(out_dil)[
                ((size_t)(b * 4 + g) * 112 + h) * 28 + cj] =
                make_float4(lft ? 1.f : 0.f, mid ? 1.f : 0.f,
                            mid ? 1.f : 0.f, rgt ? 1.f : 0.f);
        }
    }

    // ---- Finalize (CTA (0,0) only; block-uniform branch, syncs are legal) ----
    if (i == 0 && b == 0) {
        // Load full gA (25088 B = 1568 uint4) into smem, coalesced.
        for (int t = tid; t < (B_ * MH_ * MH_) / 16; t += 256)
            reinterpret_cast<uint4*>(sAll)[t] =
                reinterpret_cast<const uint4*>(gA)[t];
        // Mask count: reduce 896 per-slot counts.
        unsigned int cm = 0;
        for (int t = tid; t < B_ * MH_; t += 256) cm += g_cnt_mask[t];
        __syncthreads();

        // Dil count, closed form per coarse cell (16 fine pixels):
        //   4 interior -> 4*m
        //   8 edge     -> 2*[(m|L)+(m|R)+(m|U)+(m|D)]
        //   4 corner   -> (m|U|L|UL)+(m|U|R|UR)+(m|D|L|DL)+(m|D|R|DR)
        unsigned int cd = 0;
        for (int cell = tid; cell < B_ * MH_ * MH_; cell += 256) {
            const int bb  = cell / 784;
            const int rem = cell % 784;
            const int ci  = rem / 28;
            const int cj  = rem % 28;
            const unsigned char* A = sAll + bb * 784;
            const unsigned int m = A[ci * 28 + cj];
            const unsigned int L = (cj > 0 ) ? A[ci * 28 + cj - 1] : 0u;
            const unsigned int R = (cj < 27) ? A[ci * 28 + cj + 1] : 0u;
            const unsigned int U = (ci > 0 ) ? A[(ci - 1) * 28 + cj] : 0u;
            const unsigned int D = (ci < 27) ? A[(ci + 1) * 28 + cj] : 0u;
            const unsigned int UL = (ci > 0  && cj > 0 ) ? A[(ci - 1) * 28 + cj - 1] : 0u;
            const unsigned int UR = (ci > 0  && cj < 27) ? A[(ci - 1) * 28 + cj + 1] : 0u;
            const unsigned int DL = (ci < 27 && cj > 0 ) ? A[(ci + 1) * 28 + cj - 1] : 0u;
            const unsigned int DR = (ci < 27 && cj < 27) ? A[(ci + 1) * 28 + cj + 1] : 0u;
            cd += 4u * m
                + 2u * ((m | L) + (m | R) + (m | U) + (m | D))
                + (m | U | L | UL) + (m | U | R | UR)
                + (m | D | L | DL) + (m | D | R | DR);
        }

        // Block reduce cm, then cd.
        red[tid] = cm;
        __syncthreads();
        for (int s = 128; s > 0; s >>= 1) {
            if (tid < s) red[tid] += red[tid + s];
            __syncthreads();
        }
        const unsigned int total_cm = red[0];
        __syncthreads();
        red[tid] = cd;
        __syncthreads();
        for (int s = 128; s > 0; s >>= 1) {
            if (tid < s) red[tid] += red[tid + s];
            __syncthreads();
        }
        if (tid == 0) {
            // sparsity: fine mean == coarse mean (4x repeat preserves mean)
            out_scal[0] = (float)total_cm / (float)(B_ * G_ * MH_ * MH_);
            // sparsity_dil: identical across the G output channels
            out_scal[1] = (float)red[0] / (float)(B_ * H_ * H_);
            // flops = C*mh*mw + (8*64 + 64)*mh*mw = 501760
            out_scal[2] = 501760.0f;
        }
    }
}

extern "C" void kernel_launch(void* const* d_in, const int* in_sizes, int n_in,
                              void* d_out, int out_size)
{
    const float* x      = (const float*)d_in[0];  // (32,64,112,112)
    const float* w      = (const float*)d_in[1];  // (8,64)
    const float* bias   = (const float*)d_in[2];  // (8,)
    const float* gumbel = (const float*)d_in[3];  // (32,2,4,28,28)
    // d_in[4] = temperature: irrelevant to argmax forward values

    float* out = (float*)d_out;
    // Flattened tuple layout: [mask (N) | mask_dil (N) | sparsity, sparsity_dil, flops]
    const long long N = ((long long)out_size - 3) / 2;   // = 32*4*112*112
    float* out_mask = out;
    float* out_dil  = out + N;
    float* out_scal = out + 2 * N;

    {
        dim3 grid(MH_, B_);
        k_pool_mask<<<grid, 256>>>(x, w, bias, gumbel, out_mask);
    }
    {
        dim3 grid(MH_, B_);
        k_dil<<<grid, 256>>>(out_dil, out_scal);
    }
}